// round 14
// baseline (speedup 1.0000x reference)
#include <cuda_runtime.h>
#include <math.h>
#include <stdint.h>

#define NNODE 50000
#define NEDGE 400000
#define SDAYS 8
#define NSTEP 7
#define BPD 98  // ceil(NNODE/512)
#define NTILES ((NNODE + 63) / 64)  // 782
#define GRU_BLOCKS 296              // 74 x 4, exactly 2 blocks/SM on 148 SMs

// ---------------- device scratch (no allocation allowed) ----------------
__device__ __align__(16) float g_acc[(size_t)NSTEP * NNODE * 128];   // relu(spmm W1)+b1, all days
__device__ __align__(16) float g_x2all[(size_t)NSTEP * NNODE * 64];  // acc@W2 (day0 slot reused as h1)
__device__ __align__(16) float g_gxall[(size_t)NSTEP * NNODE * 64];  // spmm(x2)+b2, all days
__device__ __align__(16) float g_hA[(size_t)NNODE * 64];             // GRU hidden (double buffer)
__device__ __align__(16) float g_hB[(size_t)NNODE * 64];
__device__ __align__(16) float g_z[(size_t)NNODE * 128];             // [emb | neigh]
__device__ float g_stats[128];
__device__ unsigned int g_bar_cnt;
__device__ unsigned int g_bar_gen;
// 3xTF32 weight buffers (hi/lo splits)
__device__ __align__(16) uint32_t g_w2_hi[128 * 64], g_w2_lo[128 * 64];
__device__ __align__(16) uint32_t g_npw1_hi[128 * 64], g_npw1_lo[128 * 64];
__device__ __align__(16) uint32_t g_wih_hi[64 * 192], g_wih_lo[64 * 192];
__device__ __align__(16) uint32_t g_whh_hi[64 * 192], g_whh_lo[64 * 192];

// CSR structures (all 8 days)
__device__ int g_cnt[SDAYS * NNODE];
__device__ int g_self[SDAYS * NNODE];
__device__ int g_scan[SDAYS * NNODE];
__device__ int g_part[SDAYS * BPD];
__device__ int g_rowptr[SDAYS * (NNODE + 1)];
__device__ int g_cursor[SDAYS * NNODE];
__device__ int g_ecol[(size_t)SDAYS * NEDGE];
__device__ __align__(16) float g_eval[(size_t)SDAYS * NEDGE];

__device__ __forceinline__ float sigmoidf_(float x) { return 1.0f / (1.0f + expf(-x)); }

__device__ __forceinline__ uint32_t f2tf32(float x) {
    uint32_t r;
    asm("cvt.rna.tf32.f32 %0, %1;" : "=r"(r) : "f"(x));
    return r;
}
__device__ __forceinline__ void split_tf32(float x, uint32_t& hi, uint32_t& lo) {
    hi = f2tf32(x);
    lo = f2tf32(x - __uint_as_float(hi));
}

__device__ __forceinline__ void mma_tf32(float4& d, uint32_t a0, uint32_t a1, uint32_t a2,
                                         uint32_t a3, uint32_t b0, uint32_t b1) {
    asm volatile(
        "mma.sync.aligned.m16n8k8.row.col.f32.tf32.tf32.f32 "
        "{%0,%1,%2,%3}, {%4,%5,%6,%7}, {%8,%9}, {%0,%1,%2,%3};"
        : "+f"(d.x), "+f"(d.y), "+f"(d.z), "+f"(d.w)
        : "r"(a0), "r"(a1), "r"(a2), "r"(a3), "r"(b0), "r"(b1));
}

// software grid barrier: all GRU_BLOCKS blocks are co-resident (enforced by
// __launch_bounds__(256,2) + smem sizing), so spin-wait cannot deadlock.
__device__ __forceinline__ void grid_sync_() {
    __syncthreads();
    if (threadIdx.x == 0) {
        unsigned my = *(volatile unsigned*)&g_bar_gen;
        __threadfence();
        if (atomicAdd(&g_bar_cnt, 1u) == GRU_BLOCKS - 1u) {
            g_bar_cnt = 0;
            __threadfence();
            atomicAdd(&g_bar_gen, 1u);
        } else {
            while (*(volatile unsigned*)&g_bar_gen == my) { __nanosleep(64); }
        }
        __threadfence();
    }
    __syncthreads();
}

// ---------------- prep: all zeroing + weight transposes/splits in ONE launch ----------------
__global__ void prep_kernel(const float* __restrict__ w_ih, const float* __restrict__ w_hh,
                            const float* __restrict__ W2, const float* __restrict__ npw1) {
    unsigned idx = blockIdx.x * 256 + threadIdx.x;
    if (idx < 6400000u) { g_z[idx] = 0.f; return; }
    idx -= 6400000u;
    if (idx < 400000u) { g_cnt[idx] = 0; return; }
    idx -= 400000u;
    if (idx < 400000u) { g_self[idx] = 0; return; }
    idx -= 400000u;
    if (idx < 128u) { g_stats[idx] = 0.f; return; }
    idx -= 128u;
    if (idx < 2u) {
        if (idx == 0) g_bar_cnt = 0u; else g_bar_gen = 0u;
        return;
    }
    idx -= 2u;
    if (idx < 12288u) {
        int m = idx >> 6, k = idx & 63;
        uint32_t h, l;
        split_tf32(w_ih[idx], h, l);
        g_wih_hi[k * 192 + m] = h;
        g_wih_lo[k * 192 + m] = l;
        return;
    }
    idx -= 12288u;
    if (idx < 12288u) {
        int m = idx >> 6, k = idx & 63;
        uint32_t h, l;
        split_tf32(w_hh[idx], h, l);
        g_whh_hi[k * 192 + m] = h;
        g_whh_lo[k * 192 + m] = l;
        return;
    }
    idx -= 12288u;
    if (idx < 8192u) {
        uint32_t h, l;
        split_tf32(W2[idx], h, l);
        g_w2_hi[idx] = h;
        g_w2_lo[idx] = l;
        return;
    }
    idx -= 8192u;
    if (idx < 8192u) {
        uint32_t h, l;
        split_tf32(npw1[idx], h, l);
        g_npw1_hi[idx] = h;
        g_npw1_lo[idx] = l;
        return;
    }
}
#define PREP_TOTAL (6400000u + 400000u + 400000u + 128u + 2u + 12288u + 12288u + 8192u + 8192u)

// ---------------- CSR build ----------------
__global__ void csr_count_kernel(const int* __restrict__ adj_idx) {
    int idx = blockIdx.x * 256 + threadIdx.x;
    if (idx >= SDAYS * NEDGE) return;
    int d = idx / NEDGE;
    int e = idx - d * NEDGE;
    const int* base = adj_idx + (size_t)d * 2 * NEDGE;
    int r = base[e];
    int c = base[NEDGE + e];
    atomicAdd(&g_cnt[d * NNODE + r], 1);
    if (r == c) atomicAdd(&g_self[d * NNODE + r], 1);
}

__global__ void csr_scan_block_kernel() {
    __shared__ int s[512];
    int d = blockIdx.y;
    int base = blockIdx.x * 512;
    int t = threadIdx.x;
    int i0 = base + t, i1 = base + t + 256;
    s[t] = (i0 < NNODE) ? g_cnt[d * NNODE + i0] : 0;
    s[t + 256] = (i1 < NNODE) ? g_cnt[d * NNODE + i1] : 0;
    int offset = 1;
    for (int n = 256; n > 0; n >>= 1) {
        __syncthreads();
        if (t < n) {
            int ai = offset * (2 * t + 1) - 1;
            int bi = offset * (2 * t + 2) - 1;
            s[bi] += s[ai];
        }
        offset <<= 1;
    }
    if (t == 0) {
        g_part[d * BPD + blockIdx.x] = s[511];
        s[511] = 0;
    }
    for (int n = 1; n < 512; n <<= 1) {
        offset >>= 1;
        __syncthreads();
        if (t < n) {
            int ai = offset * (2 * t + 1) - 1;
            int bi = offset * (2 * t + 2) - 1;
            int tv = s[ai];
            s[ai] = s[bi];
            s[bi] += tv;
        }
    }
    __syncthreads();
    if (i0 < NNODE) g_scan[d * NNODE + i0] = s[t];
    if (i1 < NNODE) g_scan[d * NNODE + i1] = s[t + 256];
}

__global__ void csr_apply_kernel() {
    int d = blockIdx.y;
    int i = blockIdx.x * 256 + threadIdx.x;
    int lane = threadIdx.x & 31;
    int iw = blockIdx.x * 256 + (threadIdx.x & ~31);
    int nb0 = iw >> 9;
    int s = 0;
    for (int j = lane; j < nb0; j += 32) s += g_part[d * BPD + j];
#pragma unroll
    for (int o = 16; o > 0; o >>= 1) s += __shfl_xor_sync(0xffffffffu, s, o);
    int nb = i >> 9;
    if (nb > nb0) s += g_part[d * BPD + nb0];
    if (i < NNODE) {
        int v = g_scan[d * NNODE + i] + s;
        g_rowptr[d * (NNODE + 1) + i] = v;
        g_cursor[d * NNODE + i] = v;
        if (i == 0) g_rowptr[d * (NNODE + 1) + NNODE] = NEDGE;
    }
}

__global__ void csr_scatter_kernel(const int* __restrict__ adj_idx, const float* __restrict__ adj_val) {
    int idx = blockIdx.x * 256 + threadIdx.x;
    if (idx >= SDAYS * NEDGE) return;
    int d = idx / NEDGE;
    int e = idx - d * NEDGE;
    const int* base = adj_idx + (size_t)d * 2 * NEDGE;
    int r = base[e];
    int c = base[NEDGE + e];
    float v = adj_val[(size_t)d * NEDGE + e];
    int pos = atomicAdd(&g_cursor[d * NNODE + r], 1);
    g_ecol[(size_t)d * NEDGE + pos] = c;
    g_eval[(size_t)d * NEDGE + pos] = v;
}

// ---------------- K0: batched gather, warp per node, all 7 days ----------------
__global__ void __launch_bounds__(256) spmm1_gather_kernel(const int* __restrict__ p_start,
                                                           const float* __restrict__ W1,
                                                           const float* __restrict__ b1) {
    int t = blockIdx.y;
    int day = *p_start + t;
    const int* rowptr = g_rowptr + (size_t)day * (NNODE + 1);
    const int* ecol = g_ecol + (size_t)day * NEDGE;
    const float* eval = g_eval + (size_t)day * NEDGE;
    float* dst = g_acc + (size_t)t * NNODE * 128;
    int lane = threadIdx.x & 31, wid = threadIdx.x >> 5;
    int node = blockIdx.x * 8 + wid;
    if (node >= NNODE) return;
    int p0 = rowptr[node], p1 = rowptr[node + 1];
    float4 a = make_float4(0.f, 0.f, 0.f, 0.f);
    int off = lane * 4;
    int p = p0;
    for (; p + 4 <= p1; p += 4) {
        int c0 = ecol[p], c1 = ecol[p + 1], c2 = ecol[p + 2], c3 = ecol[p + 3];
        float v0 = eval[p], v1 = eval[p + 1], v2 = eval[p + 2], v3 = eval[p + 3];
        float4 w0 = *reinterpret_cast<const float4*>(W1 + (size_t)c0 * 128 + off);
        float4 w1 = *reinterpret_cast<const float4*>(W1 + (size_t)c1 * 128 + off);
        float4 w2 = *reinterpret_cast<const float4*>(W1 + (size_t)c2 * 128 + off);
        float4 w3 = *reinterpret_cast<const float4*>(W1 + (size_t)c3 * 128 + off);
        a.x = fmaf(v0, w0.x, a.x); a.y = fmaf(v0, w0.y, a.y); a.z = fmaf(v0, w0.z, a.z); a.w = fmaf(v0, w0.w, a.w);
        a.x = fmaf(v1, w1.x, a.x); a.y = fmaf(v1, w1.y, a.y); a.z = fmaf(v1, w1.z, a.z); a.w = fmaf(v1, w1.w, a.w);
        a.x = fmaf(v2, w2.x, a.x); a.y = fmaf(v2, w2.y, a.y); a.z = fmaf(v2, w2.z, a.z); a.w = fmaf(v2, w2.w, a.w);
        a.x = fmaf(v3, w3.x, a.x); a.y = fmaf(v3, w3.y, a.y); a.z = fmaf(v3, w3.z, a.z); a.w = fmaf(v3, w3.w, a.w);
    }
    for (; p < p1; p++) {
        int c0 = ecol[p];
        float v0 = eval[p];
        float4 w0 = *reinterpret_cast<const float4*>(W1 + (size_t)c0 * 128 + off);
        a.x = fmaf(v0, w0.x, a.x); a.y = fmaf(v0, w0.y, a.y); a.z = fmaf(v0, w0.z, a.z); a.w = fmaf(v0, w0.w, a.w);
    }
    float4 bb = *reinterpret_cast<const float4*>(b1 + off);
    float4 o;
    o.x = fmaxf(a.x + bb.x, 0.f);
    o.y = fmaxf(a.y + bb.y, 0.f);
    o.z = fmaxf(a.z + bb.z, 0.f);
    o.w = fmaxf(a.w + bb.w, 0.f);
    *reinterpret_cast<float4*>(dst + (size_t)node * 128 + off) = o;
}

// ---------------- K2: batched gather, half-warp per node, all 7 days ----------------
__global__ void __launch_bounds__(256) spmm2_gather_kernel(const int* __restrict__ p_start,
                                                           const float* __restrict__ b2) {
    int t = blockIdx.y;
    int day = *p_start + t;
    const int* rowptr = g_rowptr + (size_t)day * (NNODE + 1);
    const int* ecol = g_ecol + (size_t)day * NEDGE;
    const float* eval = g_eval + (size_t)day * NEDGE;
    const float* src = g_x2all + (size_t)t * NNODE * 64;
    float* dst = g_gxall + (size_t)t * NNODE * 64;
    int hw = threadIdx.x >> 4;
    int l16 = threadIdx.x & 15;
    int node = blockIdx.x * 16 + hw;
    if (node >= NNODE) return;
    int p0 = rowptr[node], p1 = rowptr[node + 1];
    float4 a = make_float4(0.f, 0.f, 0.f, 0.f);
    int off = l16 * 4;
    int p = p0;
    for (; p + 4 <= p1; p += 4) {
        int c0 = ecol[p], c1 = ecol[p + 1], c2 = ecol[p + 2], c3 = ecol[p + 3];
        float v0 = eval[p], v1 = eval[p + 1], v2 = eval[p + 2], v3 = eval[p + 3];
        float4 w0 = *reinterpret_cast<const float4*>(src + (size_t)c0 * 64 + off);
        float4 w1 = *reinterpret_cast<const float4*>(src + (size_t)c1 * 64 + off);
        float4 w2 = *reinterpret_cast<const float4*>(src + (size_t)c2 * 64 + off);
        float4 w3 = *reinterpret_cast<const float4*>(src + (size_t)c3 * 64 + off);
        a.x = fmaf(v0, w0.x, a.x); a.y = fmaf(v0, w0.y, a.y); a.z = fmaf(v0, w0.z, a.z); a.w = fmaf(v0, w0.w, a.w);
        a.x = fmaf(v1, w1.x, a.x); a.y = fmaf(v1, w1.y, a.y); a.z = fmaf(v1, w1.z, a.z); a.w = fmaf(v1, w1.w, a.w);
        a.x = fmaf(v2, w2.x, a.x); a.y = fmaf(v2, w2.y, a.y); a.z = fmaf(v2, w2.z, a.z); a.w = fmaf(v2, w2.w, a.w);
        a.x = fmaf(v3, w3.x, a.x); a.y = fmaf(v3, w3.y, a.y); a.z = fmaf(v3, w3.z, a.z); a.w = fmaf(v3, w3.w, a.w);
    }
    for (; p < p1; p++) {
        int c0 = ecol[p];
        float v0 = eval[p];
        float4 w0 = *reinterpret_cast<const float4*>(src + (size_t)c0 * 64 + off);
        a.x = fmaf(v0, w0.x, a.x); a.y = fmaf(v0, w0.y, a.y); a.z = fmaf(v0, w0.z, a.z); a.w = fmaf(v0, w0.w, a.w);
    }
    float4 bb = *reinterpret_cast<const float4*>(b2 + off);
    float4 o = make_float4(a.x + bb.x, a.y + bb.y, a.z + bb.z, a.w + bb.w);
    *reinterpret_cast<float4*>(dst + (size_t)node * 64 + off) = o;
}

// ---------------- gcn mma over ALL 7 days (persistent, B staged once) ----------------
__global__ void __launch_bounds__(256) gcn_mma_all_kernel() {
    extern __shared__ char smem_raw[];
    float* As = reinterpret_cast<float*>(smem_raw);
    uint32_t* BsH = reinterpret_cast<uint32_t*>(smem_raw + 64 * 68 * 4);
    uint32_t* BsL = BsH + 128 * 72;
    int tid = threadIdx.x, lane = tid & 31, wid = tid >> 5;
    int mt = wid >> 1, nh = wid & 1, g = lane >> 2, tg = lane & 3;

    for (int i = tid; i < 128 * 16; i += 256) {
        int k = i >> 4, n4 = (i & 15) << 2;
        *reinterpret_cast<uint4*>(&BsH[k * 72 + n4]) = *reinterpret_cast<const uint4*>(&g_w2_hi[k * 64 + n4]);
        *reinterpret_cast<uint4*>(&BsL[k * 72 + n4]) = *reinterpret_cast<const uint4*>(&g_w2_lo[k * 64 + n4]);
    }

    for (int tile = blockIdx.x; tile < NSTEP * NTILES; tile += gridDim.x) {
        int t = tile / NTILES;
        int node0 = (tile - t * NTILES) * 64;
        const float* A = g_acc + (size_t)t * NNODE * 128;
        float* out = g_x2all + (size_t)t * NNODE * 64;
        float4 acc[4];
#pragma unroll
        for (int nt = 0; nt < 4; nt++) acc[nt] = make_float4(0.f, 0.f, 0.f, 0.f);

#pragma unroll 1
        for (int chunk = 0; chunk < 2; chunk++) {
            int kc = chunk * 64;
            __syncthreads();
            for (int i = tid; i < 64 * 16; i += 256) {
                int row = i >> 4, kk = (i & 15) << 2;
                int node = node0 + row;
                float4 a = make_float4(0.f, 0.f, 0.f, 0.f);
                if (node < NNODE) a = *reinterpret_cast<const float4*>(A + (size_t)node * 128 + kc + kk);
                *reinterpret_cast<float4*>(&As[row * 68 + kk]) = a;
            }
            __syncthreads();
#pragma unroll
            for (int ks = 0; ks < 8; ks++) {
                int k0 = ks * 8;
                float a0 = As[(mt * 16 + g) * 68 + k0 + tg];
                float a1 = As[(mt * 16 + g + 8) * 68 + k0 + tg];
                float a2 = As[(mt * 16 + g) * 68 + k0 + tg + 4];
                float a3 = As[(mt * 16 + g + 8) * 68 + k0 + tg + 4];
                uint32_t ah0, al0, ah1, al1, ah2, al2, ah3, al3;
                split_tf32(a0, ah0, al0);
                split_tf32(a1, ah1, al1);
                split_tf32(a2, ah2, al2);
                split_tf32(a3, ah3, al3);
                int kb0 = (kc + k0 + tg) * 72, kb1 = (kc + k0 + tg + 4) * 72;
#pragma unroll
                for (int nt = 0; nt < 4; nt++) {
                    int n = nh * 32 + nt * 8 + g;
                    uint32_t bh0 = BsH[kb0 + n], bh1 = BsH[kb1 + n];
                    uint32_t bl0 = BsL[kb0 + n], bl1 = BsL[kb1 + n];
                    mma_tf32(acc[nt], ah0, ah1, ah2, ah3, bh0, bh1);
                    mma_tf32(acc[nt], al0, al1, al2, al3, bh0, bh1);
                    mma_tf32(acc[nt], ah0, ah1, ah2, ah3, bl0, bl1);
                }
            }
        }

        int r0 = node0 + mt * 16 + g, r1 = r0 + 8;
#pragma unroll
        for (int nt = 0; nt < 4; nt++) {
            int col = nh * 32 + nt * 8 + tg * 2;
            if (r0 < NNODE)
                *reinterpret_cast<float2*>(out + (size_t)r0 * 64 + col) = make_float2(acc[nt].x, acc[nt].y);
            if (r1 < NNODE)
                *reinterpret_cast<float2*>(out + (size_t)r1 * 64 + col) = make_float2(acc[nt].z, acc[nt].w);
        }
    }
}

// ---------------- NP head: out = A[.,128] @ B[128,64] (persistent, bias+relu) ----------
__global__ void __launch_bounds__(256) np_mma_kernel(const float* __restrict__ A,
                                                     float* __restrict__ out,
                                                     const float* __restrict__ bias) {
    extern __shared__ char smem_raw[];
    float* As = reinterpret_cast<float*>(smem_raw);
    uint32_t* BsH = reinterpret_cast<uint32_t*>(smem_raw + 64 * 68 * 4);
    uint32_t* BsL = BsH + 128 * 72;
    int tid = threadIdx.x, lane = tid & 31, wid = tid >> 5;
    int mt = wid >> 1, nh = wid & 1, g = lane >> 2, tg = lane & 3;

    for (int i = tid; i < 128 * 16; i += 256) {
        int k = i >> 4, n4 = (i & 15) << 2;
        *reinterpret_cast<uint4*>(&BsH[k * 72 + n4]) = *reinterpret_cast<const uint4*>(&g_npw1_hi[k * 64 + n4]);
        *reinterpret_cast<uint4*>(&BsL[k * 72 + n4]) = *reinterpret_cast<const uint4*>(&g_npw1_lo[k * 64 + n4]);
    }

    for (int tile = blockIdx.x; tile < NTILES; tile += gridDim.x) {
        int node0 = tile * 64;
        float4 acc[4];
#pragma unroll
        for (int nt = 0; nt < 4; nt++) acc[nt] = make_float4(0.f, 0.f, 0.f, 0.f);

#pragma unroll 1
        for (int chunk = 0; chunk < 2; chunk++) {
            int kc = chunk * 64;
            __syncthreads();
            for (int i = tid; i < 64 * 16; i += 256) {
                int row = i >> 4, kk = (i & 15) << 2;
                int node = node0 + row;
                float4 a = make_float4(0.f, 0.f, 0.f, 0.f);
                if (node < NNODE) a = *reinterpret_cast<const float4*>(A + (size_t)node * 128 + kc + kk);
                *reinterpret_cast<float4*>(&As[row * 68 + kk]) = a;
            }
            __syncthreads();
#pragma unroll
            for (int ks = 0; ks < 8; ks++) {
                int k0 = ks * 8;
                float a0 = As[(mt * 16 + g) * 68 + k0 + tg];
                float a1 = As[(mt * 16 + g + 8) * 68 + k0 + tg];
                float a2 = As[(mt * 16 + g) * 68 + k0 + tg + 4];
                float a3 = As[(mt * 16 + g + 8) * 68 + k0 + tg + 4];
                uint32_t ah0, al0, ah1, al1, ah2, al2, ah3, al3;
                split_tf32(a0, ah0, al0);
                split_tf32(a1, ah1, al1);
                split_tf32(a2, ah2, al2);
                split_tf32(a3, ah3, al3);
                int kb0 = (kc + k0 + tg) * 72, kb1 = (kc + k0 + tg + 4) * 72;
#pragma unroll
                for (int nt = 0; nt < 4; nt++) {
                    int n = nh * 32 + nt * 8 + g;
                    uint32_t bh0 = BsH[kb0 + n], bh1 = BsH[kb1 + n];
                    uint32_t bl0 = BsL[kb0 + n], bl1 = BsL[kb1 + n];
                    mma_tf32(acc[nt], ah0, ah1, ah2, ah3, bh0, bh1);
                    mma_tf32(acc[nt], al0, al1, al2, al3, bh0, bh1);
                    mma_tf32(acc[nt], ah0, ah1, ah2, ah3, bl0, bl1);
                }
            }
        }

        int r0 = node0 + mt * 16 + g, r1 = r0 + 8;
#pragma unroll
        for (int nt = 0; nt < 4; nt++) {
            int col = nh * 32 + nt * 8 + tg * 2;
            float2 bb = *reinterpret_cast<const float2*>(bias + col);
            float2 v0 = make_float2(fmaxf(acc[nt].x + bb.x, 0.f), fmaxf(acc[nt].y + bb.y, 0.f));
            float2 v1 = make_float2(fmaxf(acc[nt].z + bb.x, 0.f), fmaxf(acc[nt].w + bb.y, 0.f));
            if (r0 < NNODE) *reinterpret_cast<float2*>(out + (size_t)r0 * 64 + col) = v0;
            if (r1 < NNODE) *reinterpret_cast<float2*>(out + (size_t)r1 * 64 + col) = v1;
        }
    }
}

// ---------------- K3: PERSISTENT GRU: all 7 steps in one launch, grid-synced ----------
// grid (74,4) = 296 blocks, 2/SM enforced by __launch_bounds__(256,2).
// smem: Ax/Ah pairs 64x72 f32; 4 B-pair arrays uint2 [32][52] (staged ONCE for all steps).
__global__ void __launch_bounds__(256, 2) gru_persist_kernel(float* __restrict__ hA,
                                                             float* __restrict__ hB,
                                                             const float* __restrict__ b_ih,
                                                             const float* __restrict__ b_hh) {
    extern __shared__ char smem_raw[];
    float* Axf = reinterpret_cast<float*>(smem_raw);        // 64*72 floats
    float* Ahf = Axf + 64 * 72;                             // 64*72 floats
    uint2* BihH = reinterpret_cast<uint2*>(Ahf + 64 * 72);  // 32*52 uint2
    uint2* BihL = BihH + 32 * 52;
    uint2* BhhH = BihL + 32 * 52;
    uint2* BhhL = BhhH + 32 * 52;
    int tid = threadIdx.x, lane = tid & 31, wid = tid >> 5;
    int ny = blockIdx.y;
    int mt = wid >> 1, ns = wid & 1, g = lane >> 2, tg = lane & 3;

    // stage all B k-pair fragments ONCE for the whole recurrence
    for (int i = tid; i < 32 * 48; i += 256) {
        int r = i / 48;
        int n = i - r * 48;
        int ks = r >> 2, tg2 = r & 3;
        int k0 = ks * 8 + tg2, k1 = k0 + 4;
        int col = (n >> 4) * 64 + ny * 16 + (n & 15);
        BihH[r * 52 + n] = make_uint2(g_wih_hi[k0 * 192 + col], g_wih_hi[k1 * 192 + col]);
        BihL[r * 52 + n] = make_uint2(g_wih_lo[k0 * 192 + col], g_wih_lo[k1 * 192 + col]);
        BhhH[r * 52 + n] = make_uint2(g_whh_hi[k0 * 192 + col], g_whh_hi[k1 * 192 + col]);
        BhhL[r * 52 + n] = make_uint2(g_whh_lo[k0 * 192 + col], g_whh_lo[k1 * 192 + col]);
    }

    // loop-invariant: output columns + biases
    int jc = ny * 16 + ns * 8 + tg * 2;
    float2 bir = *reinterpret_cast<const float2*>(b_ih + jc);
    float2 biz = *reinterpret_cast<const float2*>(b_ih + 64 + jc);
    float2 bin = *reinterpret_cast<const float2*>(b_ih + 128 + jc);
    float2 bhr = *reinterpret_cast<const float2*>(b_hh + jc);
    float2 bhz = *reinterpret_cast<const float2*>(b_hh + 64 + jc);
    float2 bhn = *reinterpret_cast<const float2*>(b_hh + 128 + jc);
    int jc1 = jc + 1;
    int ofsJ0 = ((jc >> 3) * 4 + (jc & 3)) * 2 + ((jc >> 2) & 1);
    int ofsJ1 = ((jc1 >> 3) * 4 + (jc1 & 3)) * 2 + ((jc1 >> 2) & 1);
    int rowA = mt * 16 + g, rowB = rowA + 8;

#pragma unroll 1
    for (int t = 0; t < NSTEP; t++) {
        const float* gx = g_gxall + (size_t)t * NNODE * 64;
        const float* h_read = (t & 1) ? hB : hA;
        float* h_write = (t & 1) ? hA : hB;
        bool first = (t == 0);

#pragma unroll 1
        for (int tile = blockIdx.x; tile < NTILES; tile += 74) {
            int node0 = tile * 64;
            __syncthreads();
            for (int i = tid; i < 64 * 16; i += 256) {
                int row = i >> 4, kk = (i & 15) << 2;
                int node = node0 + row;
                float4 ax = make_float4(0.f, 0.f, 0.f, 0.f);
                float4 ah = make_float4(0.f, 0.f, 0.f, 0.f);
                if (node < NNODE) {
                    ax = *reinterpret_cast<const float4*>(gx + (size_t)node * 64 + kk);
                    if (!first) ah = *reinterpret_cast<const float4*>(h_read + (size_t)node * 64 + kk);
                }
                int base = row * 72 + ((kk >> 3) << 3) + ((kk >> 2) & 1);
                Axf[base + 0] = ax.x; Axf[base + 2] = ax.y; Axf[base + 4] = ax.z; Axf[base + 6] = ax.w;
                if (!first) {
                    Ahf[base + 0] = ah.x; Ahf[base + 2] = ah.y; Ahf[base + 4] = ah.z; Ahf[base + 6] = ah.w;
                }
            }
            __syncthreads();

            float4 aim[3], aic[3], ahm[3], ahc[3];
#pragma unroll
            for (int mc = 0; mc < 3; mc++) {
                aim[mc] = make_float4(0.f, 0.f, 0.f, 0.f);
                aic[mc] = make_float4(0.f, 0.f, 0.f, 0.f);
                ahm[mc] = make_float4(0.f, 0.f, 0.f, 0.f);
                ahc[mc] = make_float4(0.f, 0.f, 0.f, 0.f);
            }

#pragma unroll
            for (int ks = 0; ks < 8; ks++) {
                int pr = ks * 4 + tg;
                float2 xa = *reinterpret_cast<const float2*>(&Axf[rowA * 72 + pr * 2]);
                float2 xb = *reinterpret_cast<const float2*>(&Axf[rowB * 72 + pr * 2]);
                uint32_t xh0, xl0, xh1, xl1, xh2, xl2, xh3, xl3;
                split_tf32(xa.x, xh0, xl0); split_tf32(xb.x, xh1, xl1);
                split_tf32(xa.y, xh2, xl2); split_tf32(xb.y, xh3, xl3);
                int rb = pr * 52;
#pragma unroll
                for (int mc = 0; mc < 3; mc++) {
                    int n = mc * 16 + ns * 8 + g;
                    uint2 bih = BihH[rb + n];
                    uint2 bil = BihL[rb + n];
                    mma_tf32(aim[mc], xh0, xh1, xh2, xh3, bih.x, bih.y);
                    mma_tf32(aic[mc], xl0, xl1, xl2, xl3, bih.x, bih.y);
                    mma_tf32(aic[mc], xh0, xh1, xh2, xh3, bil.x, bil.y);
                }
                if (!first) {
                    float2 ha = *reinterpret_cast<const float2*>(&Ahf[rowA * 72 + pr * 2]);
                    float2 hb = *reinterpret_cast<const float2*>(&Ahf[rowB * 72 + pr * 2]);
                    uint32_t hh0, hl0, hh1, hl1, hh2, hl2, hh3, hl3;
                    split_tf32(ha.x, hh0, hl0); split_tf32(hb.x, hh1, hl1);
                    split_tf32(ha.y, hh2, hl2); split_tf32(hb.y, hh3, hl3);
#pragma unroll
                    for (int mc = 0; mc < 3; mc++) {
                        int n = mc * 16 + ns * 8 + g;
                        uint2 bhh = BhhH[rb + n];
                        uint2 bhl = BhhL[rb + n];
                        mma_tf32(ahm[mc], hh0, hh1, hh2, hh3, bhh.x, bhh.y);
                        mma_tf32(ahc[mc], hl0, hl1, hl2, hl3, bhh.x, bhh.y);
                        mma_tf32(ahc[mc], hh0, hh1, hh2, hh3, bhl.x, bhl.y);
                    }
                }
            }

            float4 ai[3], ahh[3];
#pragma unroll
            for (int mc = 0; mc < 3; mc++) {
                ai[mc] = make_float4(aim[mc].x + aic[mc].x, aim[mc].y + aic[mc].y,
                                     aim[mc].z + aic[mc].z, aim[mc].w + aic[mc].w);
                ahh[mc] = make_float4(ahm[mc].x + ahc[mc].x, ahm[mc].y + ahc[mc].y,
                                      ahm[mc].z + ahc[mc].z, ahm[mc].w + ahc[mc].w);
            }

            int r0 = node0 + rowA, r1 = node0 + rowB;
            if (r0 < NNODE) {
                float2 hold = first ? make_float2(0.f, 0.f)
                                    : make_float2(Ahf[rowA * 72 + ofsJ0], Ahf[rowA * 72 + ofsJ1]);
                float rr0 = sigmoidf_(ai[0].x + bir.x + ahh[0].x + bhr.x);
                float rr1 = sigmoidf_(ai[0].y + bir.y + ahh[0].y + bhr.y);
                float zz0 = sigmoidf_(ai[1].x + biz.x + ahh[1].x + bhz.x);
                float zz1 = sigmoidf_(ai[1].y + biz.y + ahh[1].y + bhz.y);
                float nn0 = tanhf(ai[2].x + bin.x + rr0 * (ahh[2].x + bhn.x));
                float nn1 = tanhf(ai[2].y + bin.y + rr1 * (ahh[2].y + bhn.y));
                *reinterpret_cast<float2*>(h_write + (size_t)r0 * 64 + jc) =
                    make_float2((1.f - zz0) * nn0 + zz0 * hold.x, (1.f - zz1) * nn1 + zz1 * hold.y);
            }
            if (r1 < NNODE) {
                float2 hold = first ? make_float2(0.f, 0.f)
                                    : make_float2(Ahf[rowB * 72 + ofsJ0], Ahf[rowB * 72 + ofsJ1]);
                float rr0 = sigmoidf_(ai[0].z + bir.x + ahh[0].z + bhr.x);
                float rr1 = sigmoidf_(ai[0].w + bir.y + ahh[0].w + bhr.y);
                float zz0 = sigmoidf_(ai[1].z + biz.x + ahh[1].z + bhz.x);
                float zz1 = sigmoidf_(ai[1].w + biz.y + ahh[1].w + bhz.y);
                float nn0 = tanhf(ai[2].z + bin.x + rr0 * (ahh[2].z + bhn.x));
                float nn1 = tanhf(ai[2].w + bin.y + rr1 * (ahh[2].w + bhn.y));
                *reinterpret_cast<float2*>(h_write + (size_t)r1 * 64 + jc) =
                    make_float2((1.f - zz0) * nn0 + zz0 * hold.x, (1.f - zz1) * nn1 + zz1 * hold.y);
            }
        }

        if (t < NSTEP - 1) grid_sync_();
    }
}

// ---------------- batch norm ----------------
__global__ void bn_stats_kernel(const float* __restrict__ h) {
    int col = threadIdx.x & 63;
    int rep = threadIdx.x >> 6;
    float s = 0.f, s2 = 0.f;
    for (int r = blockIdx.x * 4 + rep; r < NNODE; r += gridDim.x * 4) {
        float v = h[(size_t)r * 64 + col];
        s += v;
        s2 += v * v;
    }
    __shared__ float ss[4][64];
    __shared__ float ss2[4][64];
    ss[rep][col] = s;
    ss2[rep][col] = s2;
    __syncthreads();
    if (rep == 0) {
        s = ss[0][col] + ss[1][col] + ss[2][col] + ss[3][col];
        s2 = ss2[0][col] + ss2[1][col] + ss2[2][col] + ss2[3][col];
        atomicAdd(&g_stats[col], s);
        atomicAdd(&g_stats[64 + col], s2);
    }
}

__global__ void bn_norm_kernel(const float* __restrict__ h, const float* __restrict__ gamma,
                               const float* __restrict__ beta) {
    int idx = blockIdx.x * 256 + threadIdx.x;
    if (idx >= NNODE * 64) return;
    int n = idx >> 6;
    int col = idx & 63;
    float mean = g_stats[col] * (1.0f / NNODE);
    float var = g_stats[64 + col] * (1.0f / NNODE) - mean * mean;
    float inv = rsqrtf(var + 1e-5f);
    float v = (h[idx] - mean) * inv * gamma[col] + beta[col];
    g_z[(size_t)n * 128 + col] = v;
}

// ---------------- attention on day end_day+1 (deg computed from cnt-self) ----------------
__global__ void attn_kernel(const int* __restrict__ adj_idx, const int* __restrict__ end_day,
                            const float* __restrict__ aw, const float* __restrict__ ab) {
    int gid = blockIdx.x * 256 + threadIdx.x;
    int e = gid >> 5;
    if (e >= NEDGE) return;
    int lane = gid & 31;
    int day = *end_day + 1;
    const int* rowp = adj_idx + (size_t)day * 2 * NEDGE;
    int r = rowp[e];
    int c = rowp[NEDGE + e];
    if (r == c) return;
    const float* zr = g_z + (size_t)r * 128;
    const float* zc = g_z + (size_t)c * 128;
    float ec0 = zc[lane];
    float ec1 = zc[lane + 32];
    float p = zr[lane] * aw[lane] + zr[lane + 32] * aw[lane + 32] +
              ec0 * aw[64 + lane] + ec1 * aw[96 + lane];
#pragma unroll
    for (int o = 16; o > 0; o >>= 1) p += __shfl_xor_sync(0xffffffffu, p, o);
    float w = sigmoidf_(p + ab[0]);
    int di = g_cnt[day * NNODE + r] - g_self[day * NNODE + r];
    float invd = (di != 0) ? (1.0f / (float)di) : 1.0f;
    float ev = invd * w;
    atomicAdd(&g_z[(size_t)r * 128 + 64 + lane], ev * ec0);
    atomicAdd(&g_z[(size_t)r * 128 + 96 + lane], ev * ec1);
}

// ---------------- final logits + log_softmax ----------------
__global__ void logits_kernel(const float* __restrict__ w2, const float* __restrict__ b2,
                              float* __restrict__ out) {
    int gid = blockIdx.x * 256 + threadIdx.x;
    int n = gid >> 5;
    if (n >= NNODE) return;
    int lane = gid & 31;
    float v0 = g_x2all[(size_t)n * 64 + lane];
    float v1 = g_x2all[(size_t)n * 64 + 32 + lane];
    float l0 = v0 * w2[lane * 2 + 0] + v1 * w2[(lane + 32) * 2 + 0];
    float l1 = v0 * w2[lane * 2 + 1] + v1 * w2[(lane + 32) * 2 + 1];
#pragma unroll
    for (int o = 16; o > 0; o >>= 1) {
        l0 += __shfl_down_sync(0xffffffffu, l0, o);
        l1 += __shfl_down_sync(0xffffffffu, l1, o);
    }
    if (lane == 0) {
        l0 += b2[0];
        l1 += b2[1];
        float m = fmaxf(l0, l1);
        float lse = m + logf(expf(l0 - m) + expf(l1 - m));
        out[(size_t)n * 2 + 0] = l0 - lse;
        out[(size_t)n * 2 + 1] = l1 - lse;
    }
}

// ---------------- host launch ----------------
extern "C" void kernel_launch(void* const* d_in, const int* in_sizes, int n_in,
                              void* d_out, int out_size) {
    const int* adj_idx = (const int*)d_in[0];
    const float* adj_val = (const float*)d_in[1];
    const int* p_start = (const int*)d_in[2];
    const int* p_end = (const int*)d_in[3];
    const float* W1 = (const float*)d_in[4];
    const float* b1 = (const float*)d_in[5];
    const float* W2 = (const float*)d_in[6];
    const float* b2 = (const float*)d_in[7];
    const float* w_ih = (const float*)d_in[8];
    const float* w_hh = (const float*)d_in[9];
    const float* b_ih = (const float*)d_in[10];
    const float* b_hh = (const float*)d_in[11];
    const float* bn_gamma = (const float*)d_in[12];
    const float* bn_beta = (const float*)d_in[13];
    const float* attn_w = (const float*)d_in[14];
    const float* attn_b = (const float*)d_in[15];
    const float* np_w1 = (const float*)d_in[16];
    const float* np_b1 = (const float*)d_in[17];
    const float* np_w2 = (const float*)d_in[18];
    const float* np_b2 = (const float*)d_in[19];
    float* out = (float*)d_out;

    float *x2all, *hA, *hB, *z;
    cudaGetSymbolAddress((void**)&x2all, g_x2all);
    cudaGetSymbolAddress((void**)&hA, g_hA);
    cudaGetSymbolAddress((void**)&hB, g_hB);
    cudaGetSymbolAddress((void**)&z, g_z);

    const int SMEM_K1 = 64 * 68 * 4 + 2 * 128 * 72 * 4;     // 91136
    const int SMEM_K3 = 2 * 64 * 72 * 4 + 4 * 32 * 52 * 8;  // 90112
    cudaFuncSetAttribute(gcn_mma_all_kernel, cudaFuncAttributeMaxDynamicSharedMemorySize, SMEM_K1);
    cudaFuncSetAttribute(np_mma_kernel, cudaFuncAttributeMaxDynamicSharedMemorySize, SMEM_K1);
    cudaFuncSetAttribute(gru_persist_kernel, cudaFuncAttributeMaxDynamicSharedMemorySize, SMEM_K3);

    // prep + CSR build
    prep_kernel<<<(PREP_TOTAL + 255) / 256, 256>>>(w_ih, w_hh, W2, np_w1);
    csr_count_kernel<<<(SDAYS * NEDGE + 255) / 256, 256>>>(adj_idx);
    csr_scan_block_kernel<<<dim3(BPD, SDAYS), 256>>>();
    csr_apply_kernel<<<dim3((NNODE + 255) / 256, SDAYS), 256>>>();
    csr_scatter_kernel<<<(SDAYS * NEDGE + 255) / 256, 256>>>(adj_idx, adj_val);

    // ---- precompute ALL 7 days of the h-independent input path ----
    spmm1_gather_kernel<<<dim3(NNODE / 8, NSTEP), 256>>>(p_start, W1, b1);
    gcn_mma_all_kernel<<<296, 256, SMEM_K1>>>();
    spmm2_gather_kernel<<<dim3(NNODE / 16, NSTEP), 256>>>(p_start, b2);

    // ---- persistent GRU: all 7 steps, one launch, grid-synced ----
    gru_persist_kernel<<<dim3(74, 4), 256, SMEM_K3>>>(hA, hB, b_ih, b_hh);
    // after t=6 (even), final hidden state is in hB

    // ---- batch norm -> z[:, 0:64] ----
    bn_stats_kernel<<<128, 256>>>(hB);
    bn_norm_kernel<<<(NNODE * 64 + 255) / 256, 256>>>(hB, bn_gamma, bn_beta);

    // ---- attention on day end_day+1 -> z[:, 64:128] (deg from cnt-self) ----
    attn_kernel<<<(NEDGE * 32 + 255) / 256, 256>>>(adj_idx, p_end, attn_w, attn_b);

    // ---- node predictor head + logits ----
    np_mma_kernel<<<296, 256, SMEM_K1>>>(z, x2all, np_b1);
    logits_kernel<<<(NNODE * 32 + 255) / 256, 256>>>(np_w2, np_b2, out);
}

// round 15
// speedup vs baseline: 1.0458x; 1.0458x over previous
#include <cuda_runtime.h>
#include <math.h>
#include <stdint.h>

#define NNODE 50000
#define NEDGE 400000
#define SDAYS 8
#define NSTEP 7
#define BPD 98  // ceil(NNODE/512)
#define NTILES ((NNODE + 63) / 64)  // 782

// pair-interleave: pos(k) = (k>>3)*8 + (k&3)*2 + ((k>>2)&1); float2 slot pr=(ks*4+tg)
// holds (v[ks*8+tg], v[ks*8+tg+4]). inverse: k(p) = (p>>3)*8 + ((p&1)<<2) + ((p>>1)&3).

// ---------------- device scratch (no allocation allowed) ----------------
__device__ __align__(16) float g_acc[(size_t)NSTEP * NNODE * 128];   // relu(spmm W1)+b1, all days
__device__ __align__(16) float g_x2all[(size_t)NSTEP * NNODE * 64];  // acc@W2 (day0 slot reused as h1)
__device__ __align__(16) float g_gxall[(size_t)NSTEP * NNODE * 64];  // spmm(x2)+b2, PAIR layout
__device__ __align__(16) float g_hA[(size_t)NNODE * 64];             // GRU hidden, PAIR layout
__device__ __align__(16) float g_hB[(size_t)NNODE * 64];
__device__ __align__(16) float g_z[(size_t)NNODE * 128];             // [emb | neigh]
__device__ float g_stats[128];  // per-POSITION sums / sumsq
// 3xTF32 weight buffers (hi/lo splits)
__device__ __align__(16) uint32_t g_w2_hi[128 * 64], g_w2_lo[128 * 64];
__device__ __align__(16) uint32_t g_npw1_hi[128 * 64], g_npw1_lo[128 * 64];
__device__ __align__(16) uint32_t g_wih_hi[64 * 192], g_wih_lo[64 * 192];
__device__ __align__(16) uint32_t g_whh_hi[64 * 192], g_whh_lo[64 * 192];

// CSR structures (all 8 days)
__device__ int g_cnt[SDAYS * NNODE];
__device__ int g_self[SDAYS * NNODE];
__device__ int g_scan[SDAYS * NNODE];
__device__ int g_part[SDAYS * BPD];
__device__ int g_rowptr[SDAYS * (NNODE + 1)];
__device__ int g_cursor[SDAYS * NNODE];
__device__ int g_ecol[(size_t)SDAYS * NEDGE];
__device__ __align__(16) float g_eval[(size_t)SDAYS * NEDGE];

__device__ __forceinline__ float sigmoidf_(float x) { return 1.0f / (1.0f + expf(-x)); }

__device__ __forceinline__ uint32_t f2tf32(float x) {
    uint32_t r;
    asm("cvt.rna.tf32.f32 %0, %1;" : "=r"(r) : "f"(x));
    return r;
}
__device__ __forceinline__ void split_tf32(float x, uint32_t& hi, uint32_t& lo) {
    hi = f2tf32(x);
    lo = f2tf32(x - __uint_as_float(hi));
}

__device__ __forceinline__ void mma_tf32(float4& d, uint32_t a0, uint32_t a1, uint32_t a2,
                                         uint32_t a3, uint32_t b0, uint32_t b1) {
    asm volatile(
        "mma.sync.aligned.m16n8k8.row.col.f32.tf32.tf32.f32 "
        "{%0,%1,%2,%3}, {%4,%5,%6,%7}, {%8,%9}, {%0,%1,%2,%3};"
        : "+f"(d.x), "+f"(d.y), "+f"(d.z), "+f"(d.w)
        : "r"(a0), "r"(a1), "r"(a2), "r"(a3), "r"(b0), "r"(b1));
}

// ---------------- prep: zeroing + weight transposes/splits in ONE launch ----------------
__global__ void prep_kernel(const float* __restrict__ w_ih, const float* __restrict__ w_hh,
                            const float* __restrict__ W2, const float* __restrict__ npw1) {
    unsigned idx = blockIdx.x * 256 + threadIdx.x;
    if (idx < 3200000u) {  // zero only z upper half (attn accumulator)
        unsigned n = idx >> 6, col = idx & 63u;
        g_z[(size_t)n * 128 + 64 + col] = 0.f;
        return;
    }
    idx -= 3200000u;
    if (idx < 400000u) { g_cnt[idx] = 0; return; }
    idx -= 400000u;
    if (idx < 400000u) { g_self[idx] = 0; return; }
    idx -= 400000u;
    if (idx < 128u) { g_stats[idx] = 0.f; return; }
    idx -= 128u;
    if (idx < 12288u) {
        int m = idx >> 6, k = idx & 63;
        uint32_t h, l;
        split_tf32(w_ih[idx], h, l);
        g_wih_hi[k * 192 + m] = h;
        g_wih_lo[k * 192 + m] = l;
        return;
    }
    idx -= 12288u;
    if (idx < 12288u) {
        int m = idx >> 6, k = idx & 63;
        uint32_t h, l;
        split_tf32(w_hh[idx], h, l);
        g_whh_hi[k * 192 + m] = h;
        g_whh_lo[k * 192 + m] = l;
        return;
    }
    idx -= 12288u;
    if (idx < 8192u) {
        uint32_t h, l;
        split_tf32(W2[idx], h, l);
        g_w2_hi[idx] = h;
        g_w2_lo[idx] = l;
        return;
    }
    idx -= 8192u;
    if (idx < 8192u) {
        uint32_t h, l;
        split_tf32(npw1[idx], h, l);
        g_npw1_hi[idx] = h;
        g_npw1_lo[idx] = l;
        return;
    }
}
#define PREP_TOTAL (3200000u + 400000u + 400000u + 128u + 12288u + 12288u + 8192u + 8192u)

// ---------------- CSR build ----------------
__global__ void csr_count_kernel(const int* __restrict__ adj_idx) {
    int idx = blockIdx.x * 256 + threadIdx.x;
    if (idx >= SDAYS * NEDGE) return;
    int d = idx / NEDGE;
    int e = idx - d * NEDGE;
    const int* base = adj_idx + (size_t)d * 2 * NEDGE;
    int r = base[e];
    int c = base[NEDGE + e];
    atomicAdd(&g_cnt[d * NNODE + r], 1);
    if (r == c) atomicAdd(&g_self[d * NNODE + r], 1);
}

__global__ void csr_scan_block_kernel() {
    __shared__ int s[512];
    int d = blockIdx.y;
    int base = blockIdx.x * 512;
    int t = threadIdx.x;
    int i0 = base + t, i1 = base + t + 256;
    s[t] = (i0 < NNODE) ? g_cnt[d * NNODE + i0] : 0;
    s[t + 256] = (i1 < NNODE) ? g_cnt[d * NNODE + i1] : 0;
    int offset = 1;
    for (int n = 256; n > 0; n >>= 1) {
        __syncthreads();
        if (t < n) {
            int ai = offset * (2 * t + 1) - 1;
            int bi = offset * (2 * t + 2) - 1;
            s[bi] += s[ai];
        }
        offset <<= 1;
    }
    if (t == 0) {
        g_part[d * BPD + blockIdx.x] = s[511];
        s[511] = 0;
    }
    for (int n = 1; n < 512; n <<= 1) {
        offset >>= 1;
        __syncthreads();
        if (t < n) {
            int ai = offset * (2 * t + 1) - 1;
            int bi = offset * (2 * t + 2) - 1;
            int tv = s[ai];
            s[ai] = s[bi];
            s[bi] += tv;
        }
    }
    __syncthreads();
    if (i0 < NNODE) g_scan[d * NNODE + i0] = s[t];
    if (i1 < NNODE) g_scan[d * NNODE + i1] = s[t + 256];
}

__global__ void csr_apply_kernel() {
    int d = blockIdx.y;
    int i = blockIdx.x * 256 + threadIdx.x;
    int lane = threadIdx.x & 31;
    int iw = blockIdx.x * 256 + (threadIdx.x & ~31);
    int nb0 = iw >> 9;
    int s = 0;
    for (int j = lane; j < nb0; j += 32) s += g_part[d * BPD + j];
#pragma unroll
    for (int o = 16; o > 0; o >>= 1) s += __shfl_xor_sync(0xffffffffu, s, o);
    int nb = i >> 9;
    if (nb > nb0) s += g_part[d * BPD + nb0];
    if (i < NNODE) {
        int v = g_scan[d * NNODE + i] + s;
        g_rowptr[d * (NNODE + 1) + i] = v;
        g_cursor[d * NNODE + i] = v;
        if (i == 0) g_rowptr[d * (NNODE + 1) + NNODE] = NEDGE;
    }
}

__global__ void csr_scatter_kernel(const int* __restrict__ adj_idx, const float* __restrict__ adj_val) {
    int idx = blockIdx.x * 256 + threadIdx.x;
    if (idx >= SDAYS * NEDGE) return;
    int d = idx / NEDGE;
    int e = idx - d * NEDGE;
    const int* base = adj_idx + (size_t)d * 2 * NEDGE;
    int r = base[e];
    int c = base[NEDGE + e];
    float v = adj_val[(size_t)d * NEDGE + e];
    int pos = atomicAdd(&g_cursor[d * NNODE + r], 1);
    g_ecol[(size_t)d * NEDGE + pos] = c;
    g_eval[(size_t)d * NEDGE + pos] = v;
}

// ---------------- K0: batched gather, warp per node, all 7 days ----------------
__global__ void __launch_bounds__(256) spmm1_gather_kernel(const int* __restrict__ p_start,
                                                           const float* __restrict__ W1,
                                                           const float* __restrict__ b1) {
    int t = blockIdx.y;
    int day = *p_start + t;
    const int* rowptr = g_rowptr + (size_t)day * (NNODE + 1);
    const int* ecol = g_ecol + (size_t)day * NEDGE;
    const float* eval = g_eval + (size_t)day * NEDGE;
    float* dst = g_acc + (size_t)t * NNODE * 128;
    int lane = threadIdx.x & 31, wid = threadIdx.x >> 5;
    int node = blockIdx.x * 8 + wid;
    if (node >= NNODE) return;
    int p0 = rowptr[node], p1 = rowptr[node + 1];
    float4 a = make_float4(0.f, 0.f, 0.f, 0.f);
    int off = lane * 4;
    int p = p0;
    for (; p + 4 <= p1; p += 4) {
        int c0 = ecol[p], c1 = ecol[p + 1], c2 = ecol[p + 2], c3 = ecol[p + 3];
        float v0 = eval[p], v1 = eval[p + 1], v2 = eval[p + 2], v3 = eval[p + 3];
        float4 w0 = *reinterpret_cast<const float4*>(W1 + (size_t)c0 * 128 + off);
        float4 w1 = *reinterpret_cast<const float4*>(W1 + (size_t)c1 * 128 + off);
        float4 w2 = *reinterpret_cast<const float4*>(W1 + (size_t)c2 * 128 + off);
        float4 w3 = *reinterpret_cast<const float4*>(W1 + (size_t)c3 * 128 + off);
        a.x = fmaf(v0, w0.x, a.x); a.y = fmaf(v0, w0.y, a.y); a.z = fmaf(v0, w0.z, a.z); a.w = fmaf(v0, w0.w, a.w);
        a.x = fmaf(v1, w1.x, a.x); a.y = fmaf(v1, w1.y, a.y); a.z = fmaf(v1, w1.z, a.z); a.w = fmaf(v1, w1.w, a.w);
        a.x = fmaf(v2, w2.x, a.x); a.y = fmaf(v2, w2.y, a.y); a.z = fmaf(v2, w2.z, a.z); a.w = fmaf(v2, w2.w, a.w);
        a.x = fmaf(v3, w3.x, a.x); a.y = fmaf(v3, w3.y, a.y); a.z = fmaf(v3, w3.z, a.z); a.w = fmaf(v3, w3.w, a.w);
    }
    for (; p < p1; p++) {
        int c0 = ecol[p];
        float v0 = eval[p];
        float4 w0 = *reinterpret_cast<const float4*>(W1 + (size_t)c0 * 128 + off);
        a.x = fmaf(v0, w0.x, a.x); a.y = fmaf(v0, w0.y, a.y); a.z = fmaf(v0, w0.z, a.z); a.w = fmaf(v0, w0.w, a.w);
    }
    float4 bb = *reinterpret_cast<const float4*>(b1 + off);
    float4 o;
    o.x = fmaxf(a.x + bb.x, 0.f);
    o.y = fmaxf(a.y + bb.y, 0.f);
    o.z = fmaxf(a.z + bb.z, 0.f);
    o.w = fmaxf(a.w + bb.w, 0.f);
    *reinterpret_cast<float4*>(dst + (size_t)node * 128 + off) = o;
}

// ---------------- K2: batched gather -> gx in PAIR layout, all 7 days ----------------
__global__ void __launch_bounds__(256) spmm2_gather_kernel(const int* __restrict__ p_start,
                                                           const float* __restrict__ b2) {
    int t = blockIdx.y;
    int day = *p_start + t;
    const int* rowptr = g_rowptr + (size_t)day * (NNODE + 1);
    const int* ecol = g_ecol + (size_t)day * NEDGE;
    const float* eval = g_eval + (size_t)day * NEDGE;
    const float* src = g_x2all + (size_t)t * NNODE * 64;
    float* dst = g_gxall + (size_t)t * NNODE * 64;
    int hw = threadIdx.x >> 4;
    int l16 = threadIdx.x & 15;
    int node = blockIdx.x * 16 + hw;
    if (node >= NNODE) return;
    int p0 = rowptr[node], p1 = rowptr[node + 1];
    float4 a = make_float4(0.f, 0.f, 0.f, 0.f);
    int off = l16 * 4;
    int p = p0;
    for (; p + 4 <= p1; p += 4) {
        int c0 = ecol[p], c1 = ecol[p + 1], c2 = ecol[p + 2], c3 = ecol[p + 3];
        float v0 = eval[p], v1 = eval[p + 1], v2 = eval[p + 2], v3 = eval[p + 3];
        float4 w0 = *reinterpret_cast<const float4*>(src + (size_t)c0 * 64 + off);
        float4 w1 = *reinterpret_cast<const float4*>(src + (size_t)c1 * 64 + off);
        float4 w2 = *reinterpret_cast<const float4*>(src + (size_t)c2 * 64 + off);
        float4 w3 = *reinterpret_cast<const float4*>(src + (size_t)c3 * 64 + off);
        a.x = fmaf(v0, w0.x, a.x); a.y = fmaf(v0, w0.y, a.y); a.z = fmaf(v0, w0.z, a.z); a.w = fmaf(v0, w0.w, a.w);
        a.x = fmaf(v1, w1.x, a.x); a.y = fmaf(v1, w1.y, a.y); a.z = fmaf(v1, w1.z, a.z); a.w = fmaf(v1, w1.w, a.w);
        a.x = fmaf(v2, w2.x, a.x); a.y = fmaf(v2, w2.y, a.y); a.z = fmaf(v2, w2.z, a.z); a.w = fmaf(v2, w2.w, a.w);
        a.x = fmaf(v3, w3.x, a.x); a.y = fmaf(v3, w3.y, a.y); a.z = fmaf(v3, w3.z, a.z); a.w = fmaf(v3, w3.w, a.w);
    }
    for (; p < p1; p++) {
        int c0 = ecol[p];
        float v0 = eval[p];
        float4 w0 = *reinterpret_cast<const float4*>(src + (size_t)c0 * 64 + off);
        a.x = fmaf(v0, w0.x, a.x); a.y = fmaf(v0, w0.y, a.y); a.z = fmaf(v0, w0.z, a.z); a.w = fmaf(v0, w0.w, a.w);
    }
    float4 bb = *reinterpret_cast<const float4*>(b2 + off);
    // pair-interleaved store: cols off..off+3 -> base + {0,2,4,6}
    float* d0 = dst + (size_t)node * 64 + ((off >> 3) << 3) + ((off >> 2) & 1);
    d0[0] = a.x + bb.x;
    d0[2] = a.y + bb.y;
    d0[4] = a.z + bb.z;
    d0[6] = a.w + bb.w;
}

// ---------------- gcn mma over ALL 7 days (persistent, B staged once) ----------------
__global__ void __launch_bounds__(256) gcn_mma_all_kernel() {
    extern __shared__ char smem_raw[];
    float* As = reinterpret_cast<float*>(smem_raw);
    uint32_t* BsH = reinterpret_cast<uint32_t*>(smem_raw + 64 * 68 * 4);
    uint32_t* BsL = BsH + 128 * 72;
    int tid = threadIdx.x, lane = tid & 31, wid = tid >> 5;
    int mt = wid >> 1, nh = wid & 1, g = lane >> 2, tg = lane & 3;

    for (int i = tid; i < 128 * 16; i += 256) {
        int k = i >> 4, n4 = (i & 15) << 2;
        *reinterpret_cast<uint4*>(&BsH[k * 72 + n4]) = *reinterpret_cast<const uint4*>(&g_w2_hi[k * 64 + n4]);
        *reinterpret_cast<uint4*>(&BsL[k * 72 + n4]) = *reinterpret_cast<const uint4*>(&g_w2_lo[k * 64 + n4]);
    }

    for (int tile = blockIdx.x; tile < NSTEP * NTILES; tile += gridDim.x) {
        int t = tile / NTILES;
        int node0 = (tile - t * NTILES) * 64;
        const float* A = g_acc + (size_t)t * NNODE * 128;
        float* out = g_x2all + (size_t)t * NNODE * 64;
        float4 acc[4];
#pragma unroll
        for (int nt = 0; nt < 4; nt++) acc[nt] = make_float4(0.f, 0.f, 0.f, 0.f);

#pragma unroll 1
        for (int chunk = 0; chunk < 2; chunk++) {
            int kc = chunk * 64;
            __syncthreads();
            for (int i = tid; i < 64 * 16; i += 256) {
                int row = i >> 4, kk = (i & 15) << 2;
                int node = node0 + row;
                float4 a = make_float4(0.f, 0.f, 0.f, 0.f);
                if (node < NNODE) a = *reinterpret_cast<const float4*>(A + (size_t)node * 128 + kc + kk);
                *reinterpret_cast<float4*>(&As[row * 68 + kk]) = a;
            }
            __syncthreads();
#pragma unroll
            for (int ks = 0; ks < 8; ks++) {
                int k0 = ks * 8;
                float a0 = As[(mt * 16 + g) * 68 + k0 + tg];
                float a1 = As[(mt * 16 + g + 8) * 68 + k0 + tg];
                float a2 = As[(mt * 16 + g) * 68 + k0 + tg + 4];
                float a3 = As[(mt * 16 + g + 8) * 68 + k0 + tg + 4];
                uint32_t ah0, al0, ah1, al1, ah2, al2, ah3, al3;
                split_tf32(a0, ah0, al0);
                split_tf32(a1, ah1, al1);
                split_tf32(a2, ah2, al2);
                split_tf32(a3, ah3, al3);
                int kb0 = (kc + k0 + tg) * 72, kb1 = (kc + k0 + tg + 4) * 72;
#pragma unroll
                for (int nt = 0; nt < 4; nt++) {
                    int n = nh * 32 + nt * 8 + g;
                    uint32_t bh0 = BsH[kb0 + n], bh1 = BsH[kb1 + n];
                    uint32_t bl0 = BsL[kb0 + n], bl1 = BsL[kb1 + n];
                    mma_tf32(acc[nt], ah0, ah1, ah2, ah3, bh0, bh1);
                    mma_tf32(acc[nt], al0, al1, al2, al3, bh0, bh1);
                    mma_tf32(acc[nt], ah0, ah1, ah2, ah3, bl0, bl1);
                }
            }
        }

        int r0 = node0 + mt * 16 + g, r1 = r0 + 8;
#pragma unroll
        for (int nt = 0; nt < 4; nt++) {
            int col = nh * 32 + nt * 8 + tg * 2;
            if (r0 < NNODE)
                *reinterpret_cast<float2*>(out + (size_t)r0 * 64 + col) = make_float2(acc[nt].x, acc[nt].y);
            if (r1 < NNODE)
                *reinterpret_cast<float2*>(out + (size_t)r1 * 64 + col) = make_float2(acc[nt].z, acc[nt].w);
        }
    }
}

// ---------------- NP head: out = A[.,128] @ B[128,64] (persistent, bias+relu) ----------
__global__ void __launch_bounds__(256) np_mma_kernel(const float* __restrict__ A,
                                                     float* __restrict__ out,
                                                     const float* __restrict__ bias) {
    extern __shared__ char smem_raw[];
    float* As = reinterpret_cast<float*>(smem_raw);
    uint32_t* BsH = reinterpret_cast<uint32_t*>(smem_raw + 64 * 68 * 4);
    uint32_t* BsL = BsH + 128 * 72;
    int tid = threadIdx.x, lane = tid & 31, wid = tid >> 5;
    int mt = wid >> 1, nh = wid & 1, g = lane >> 2, tg = lane & 3;

    for (int i = tid; i < 128 * 16; i += 256) {
        int k = i >> 4, n4 = (i & 15) << 2;
        *reinterpret_cast<uint4*>(&BsH[k * 72 + n4]) = *reinterpret_cast<const uint4*>(&g_npw1_hi[k * 64 + n4]);
        *reinterpret_cast<uint4*>(&BsL[k * 72 + n4]) = *reinterpret_cast<const uint4*>(&g_npw1_lo[k * 64 + n4]);
    }

    for (int tile = blockIdx.x; tile < NTILES; tile += gridDim.x) {
        int node0 = tile * 64;
        float4 acc[4];
#pragma unroll
        for (int nt = 0; nt < 4; nt++) acc[nt] = make_float4(0.f, 0.f, 0.f, 0.f);

#pragma unroll 1
        for (int chunk = 0; chunk < 2; chunk++) {
            int kc = chunk * 64;
            __syncthreads();
            for (int i = tid; i < 64 * 16; i += 256) {
                int row = i >> 4, kk = (i & 15) << 2;
                int node = node0 + row;
                float4 a = make_float4(0.f, 0.f, 0.f, 0.f);
                if (node < NNODE) a = *reinterpret_cast<const float4*>(A + (size_t)node * 128 + kc + kk);
                *reinterpret_cast<float4*>(&As[row * 68 + kk]) = a;
            }
            __syncthreads();
#pragma unroll
            for (int ks = 0; ks < 8; ks++) {
                int k0 = ks * 8;
                float a0 = As[(mt * 16 + g) * 68 + k0 + tg];
                float a1 = As[(mt * 16 + g + 8) * 68 + k0 + tg];
                float a2 = As[(mt * 16 + g) * 68 + k0 + tg + 4];
                float a3 = As[(mt * 16 + g + 8) * 68 + k0 + tg + 4];
                uint32_t ah0, al0, ah1, al1, ah2, al2, ah3, al3;
                split_tf32(a0, ah0, al0);
                split_tf32(a1, ah1, al1);
                split_tf32(a2, ah2, al2);
                split_tf32(a3, ah3, al3);
                int kb0 = (kc + k0 + tg) * 72, kb1 = (kc + k0 + tg + 4) * 72;
#pragma unroll
                for (int nt = 0; nt < 4; nt++) {
                    int n = nh * 32 + nt * 8 + g;
                    uint32_t bh0 = BsH[kb0 + n], bh1 = BsH[kb1 + n];
                    uint32_t bl0 = BsL[kb0 + n], bl1 = BsL[kb1 + n];
                    mma_tf32(acc[nt], ah0, ah1, ah2, ah3, bh0, bh1);
                    mma_tf32(acc[nt], al0, al1, al2, al3, bh0, bh1);
                    mma_tf32(acc[nt], ah0, ah1, ah2, ah3, bl0, bl1);
                }
            }
        }

        int r0 = node0 + mt * 16 + g, r1 = r0 + 8;
#pragma unroll
        for (int nt = 0; nt < 4; nt++) {
            int col = nh * 32 + nt * 8 + tg * 2;
            float2 bb = *reinterpret_cast<const float2*>(bias + col);
            float2 v0 = make_float2(fmaxf(acc[nt].x + bb.x, 0.f), fmaxf(acc[nt].y + bb.y, 0.f));
            float2 v1 = make_float2(fmaxf(acc[nt].z + bb.x, 0.f), fmaxf(acc[nt].w + bb.y, 0.f));
            if (r0 < NNODE) *reinterpret_cast<float2*>(out + (size_t)r0 * 64 + col) = v0;
            if (r1 < NNODE) *reinterpret_cast<float2*>(out + (size_t)r1 * 64 + col) = v1;
        }
    }
}

// ---------------- K3: GRU, NO A-staging: direct pair-layout LDG fragments ----------
// grid (111,4) = 444 blocks, 3 blocks/SM. smem = B pairs only (53KB). One sync total.
template <bool FIRST>
__global__ void __launch_bounds__(256, 3) gru_mma_kernel(const float* __restrict__ gx,
                                                         const float* __restrict__ h_read,
                                                         float* __restrict__ h_write,
                                                         const float* __restrict__ b_ih,
                                                         const float* __restrict__ b_hh, int ntiles) {
    extern __shared__ char smem_raw[];
    uint2* BihH = reinterpret_cast<uint2*>(smem_raw);  // 32*52 uint2
    uint2* BihL = BihH + 32 * 52;
    uint2* BhhH = BihL + 32 * 52;
    uint2* BhhL = BhhH + 32 * 52;
    int tid = threadIdx.x, lane = tid & 31, wid = tid >> 5;
    int ny = blockIdx.y;
    int mt = wid >> 1, ns = wid & 1, g = lane >> 2, tg = lane & 3;

    // stage B k-pair fragments ONCE
    for (int i = tid; i < 32 * 48; i += 256) {
        int r = i / 48;
        int n = i - r * 48;
        int ks = r >> 2, tg2 = r & 3;
        int k0 = ks * 8 + tg2, k1 = k0 + 4;
        int col = (n >> 4) * 64 + ny * 16 + (n & 15);
        BihH[r * 52 + n] = make_uint2(g_wih_hi[k0 * 192 + col], g_wih_hi[k1 * 192 + col]);
        BihL[r * 52 + n] = make_uint2(g_wih_lo[k0 * 192 + col], g_wih_lo[k1 * 192 + col]);
        if (!FIRST) {
            BhhH[r * 52 + n] = make_uint2(g_whh_hi[k0 * 192 + col], g_whh_hi[k1 * 192 + col]);
            BhhL[r * 52 + n] = make_uint2(g_whh_lo[k0 * 192 + col], g_whh_lo[k1 * 192 + col]);
        }
    }
    __syncthreads();

    // loop-invariant: output columns + biases
    int jc = ny * 16 + ns * 8 + tg * 2;
    float2 bir = *reinterpret_cast<const float2*>(b_ih + jc);
    float2 biz = *reinterpret_cast<const float2*>(b_ih + 64 + jc);
    float2 bin = *reinterpret_cast<const float2*>(b_ih + 128 + jc);
    float2 bhr = *reinterpret_cast<const float2*>(b_hh + jc);
    float2 bhz = *reinterpret_cast<const float2*>(b_hh + 64 + jc);
    float2 bhn = *reinterpret_cast<const float2*>(b_hh + 128 + jc);
    // pair-layout position of jc (jc+1 is at +2)
    int posJ = ((jc >> 3) << 3) + ((jc & 3) << 1) + ((jc >> 2) & 1);
    int rowA = mt * 16 + g, rowB = rowA + 8;

#pragma unroll 1
    for (int tile = blockIdx.x; tile < ntiles; tile += gridDim.x) {
        int node0 = tile * 64;
        int r0 = node0 + rowA, r1 = node0 + rowB;
        bool va = r0 < NNODE, vb = r1 < NNODE;
        const float* gxA = gx + (size_t)r0 * 64;
        const float* gxB = gx + (size_t)r1 * 64;
        const float* hA_ = h_read + (size_t)r0 * 64;
        const float* hB_ = h_read + (size_t)r1 * 64;

        float4 aim[3], aic[3], ahm[3], ahc[3];
#pragma unroll
        for (int mc = 0; mc < 3; mc++) {
            aim[mc] = make_float4(0.f, 0.f, 0.f, 0.f);
            aic[mc] = make_float4(0.f, 0.f, 0.f, 0.f);
            ahm[mc] = make_float4(0.f, 0.f, 0.f, 0.f);
            ahc[mc] = make_float4(0.f, 0.f, 0.f, 0.f);
        }

#pragma unroll
        for (int ks = 0; ks < 8; ks++) {
            int pr = ks * 4 + tg;
            float2 xa = va ? __ldg(reinterpret_cast<const float2*>(gxA + pr * 2)) : make_float2(0.f, 0.f);
            float2 xb = vb ? __ldg(reinterpret_cast<const float2*>(gxB + pr * 2)) : make_float2(0.f, 0.f);
            uint32_t xh0, xl0, xh1, xl1, xh2, xl2, xh3, xl3;
            split_tf32(xa.x, xh0, xl0); split_tf32(xb.x, xh1, xl1);
            split_tf32(xa.y, xh2, xl2); split_tf32(xb.y, xh3, xl3);
            int rb = pr * 52;
#pragma unroll
            for (int mc = 0; mc < 3; mc++) {
                int n = mc * 16 + ns * 8 + g;
                uint2 bih = BihH[rb + n];
                uint2 bil = BihL[rb + n];
                mma_tf32(aim[mc], xh0, xh1, xh2, xh3, bih.x, bih.y);
                mma_tf32(aic[mc], xl0, xl1, xl2, xl3, bih.x, bih.y);
                mma_tf32(aic[mc], xh0, xh1, xh2, xh3, bil.x, bil.y);
            }
            if (!FIRST) {
                float2 ha = va ? __ldg(reinterpret_cast<const float2*>(hA_ + pr * 2)) : make_float2(0.f, 0.f);
                float2 hb = vb ? __ldg(reinterpret_cast<const float2*>(hB_ + pr * 2)) : make_float2(0.f, 0.f);
                uint32_t hh0, hl0, hh1, hl1, hh2, hl2, hh3, hl3;
                split_tf32(ha.x, hh0, hl0); split_tf32(hb.x, hh1, hl1);
                split_tf32(ha.y, hh2, hl2); split_tf32(hb.y, hh3, hl3);
#pragma unroll
                for (int mc = 0; mc < 3; mc++) {
                    int n = mc * 16 + ns * 8 + g;
                    uint2 bhh = BhhH[rb + n];
                    uint2 bhl = BhhL[rb + n];
                    mma_tf32(ahm[mc], hh0, hh1, hh2, hh3, bhh.x, bhh.y);
                    mma_tf32(ahc[mc], hl0, hl1, hl2, hl3, bhh.x, bhh.y);
                    mma_tf32(ahc[mc], hh0, hh1, hh2, hh3, bhl.x, bhl.y);
                }
            }
        }

        float4 ai[3], ahh[3];
#pragma unroll
        for (int mc = 0; mc < 3; mc++) {
            ai[mc] = make_float4(aim[mc].x + aic[mc].x, aim[mc].y + aic[mc].y,
                                 aim[mc].z + aic[mc].z, aim[mc].w + aic[mc].w);
            ahh[mc] = make_float4(ahm[mc].x + ahc[mc].x, ahm[mc].y + ahc[mc].y,
                                  ahm[mc].z + ahc[mc].z, ahm[mc].w + ahc[mc].w);
        }

        if (va) {
            float h0 = FIRST ? 0.f : __ldg(hA_ + posJ);
            float h1 = FIRST ? 0.f : __ldg(hA_ + posJ + 2);
            float rr0 = sigmoidf_(ai[0].x + bir.x + ahh[0].x + bhr.x);
            float rr1 = sigmoidf_(ai[0].y + bir.y + ahh[0].y + bhr.y);
            float zz0 = sigmoidf_(ai[1].x + biz.x + ahh[1].x + bhz.x);
            float zz1 = sigmoidf_(ai[1].y + biz.y + ahh[1].y + bhz.y);
            float nn0 = tanhf(ai[2].x + bin.x + rr0 * (ahh[2].x + bhn.x));
            float nn1 = tanhf(ai[2].y + bin.y + rr1 * (ahh[2].y + bhn.y));
            float* hw = h_write + (size_t)r0 * 64;
            hw[posJ] = (1.f - zz0) * nn0 + zz0 * h0;
            hw[posJ + 2] = (1.f - zz1) * nn1 + zz1 * h1;
        }
        if (vb) {
            float h0 = FIRST ? 0.f : __ldg(hB_ + posJ);
            float h1 = FIRST ? 0.f : __ldg(hB_ + posJ + 2);
            float rr0 = sigmoidf_(ai[0].z + bir.x + ahh[0].z + bhr.x);
            float rr1 = sigmoidf_(ai[0].w + bir.y + ahh[0].w + bhr.y);
            float zz0 = sigmoidf_(ai[1].z + biz.x + ahh[1].z + bhz.x);
            float zz1 = sigmoidf_(ai[1].w + biz.y + ahh[1].w + bhz.y);
            float nn0 = tanhf(ai[2].z + bin.x + rr0 * (ahh[2].z + bhn.x));
            float nn1 = tanhf(ai[2].w + bin.y + rr1 * (ahh[2].w + bhn.y));
            float* hw = h_write + (size_t)r1 * 64;
            hw[posJ] = (1.f - zz0) * nn0 + zz0 * h0;
            hw[posJ + 2] = (1.f - zz1) * nn1 + zz1 * h1;
        }
    }
}

// ---------------- batch norm (h is in PAIR layout; stats indexed by position) --------
__global__ void bn_stats_kernel(const float* __restrict__ h) {
    int col = threadIdx.x & 63;  // position
    int rep = threadIdx.x >> 6;
    float s = 0.f, s2 = 0.f;
    for (int r = blockIdx.x * 4 + rep; r < NNODE; r += gridDim.x * 4) {
        float v = h[(size_t)r * 64 + col];
        s += v;
        s2 += v * v;
    }
    __shared__ float ss[4][64];
    __shared__ float ss2[4][64];
    ss[rep][col] = s;
    ss2[rep][col] = s2;
    __syncthreads();
    if (rep == 0) {
        s = ss[0][col] + ss[1][col] + ss[2][col] + ss[3][col];
        s2 = ss2[0][col] + ss2[1][col] + ss2[2][col] + ss2[3][col];
        atomicAdd(&g_stats[col], s);
        atomicAdd(&g_stats[64 + col], s2);
    }
}

__global__ void bn_norm_kernel(const float* __restrict__ h, const float* __restrict__ gamma,
                               const float* __restrict__ beta) {
    int idx = blockIdx.x * 256 + threadIdx.x;
    if (idx >= NNODE * 64) return;
    int n = idx >> 6;
    int p = idx & 63;  // position in pair layout
    int col = ((p >> 3) << 3) + ((p & 1) << 2) + ((p >> 1) & 3);  // real column
    float mean = g_stats[p] * (1.0f / NNODE);
    float var = g_stats[64 + p] * (1.0f / NNODE) - mean * mean;
    float inv = rsqrtf(var + 1e-5f);
    float v = (h[idx] - mean) * inv * gamma[col] + beta[col];
    g_z[(size_t)n * 128 + col] = v;
}

// ---------------- attention on day end_day+1 (deg computed from cnt-self) ----------------
__global__ void attn_kernel(const int* __restrict__ adj_idx, const int* __restrict__ end_day,
                            const float* __restrict__ aw, const float* __restrict__ ab) {
    int gid = blockIdx.x * 256 + threadIdx.x;
    int e = gid >> 5;
    if (e >= NEDGE) return;
    int lane = gid & 31;
    int day = *end_day + 1;
    const int* rowp = adj_idx + (size_t)day * 2 * NEDGE;
    int r = rowp[e];
    int c = rowp[NEDGE + e];
    if (r == c) return;
    const float* zr = g_z + (size_t)r * 128;
    const float* zc = g_z + (size_t)c * 128;
    float ec0 = zc[lane];
    float ec1 = zc[lane + 32];
    float p = zr[lane] * aw[lane] + zr[lane + 32] * aw[lane + 32] +
              ec0 * aw[64 + lane] + ec1 * aw[96 + lane];
#pragma unroll
    for (int o = 16; o > 0; o >>= 1) p += __shfl_xor_sync(0xffffffffu, p, o);
    float w = sigmoidf_(p + ab[0]);
    int di = g_cnt[day * NNODE + r] - g_self[day * NNODE + r];
    float invd = (di != 0) ? (1.0f / (float)di) : 1.0f;
    float ev = invd * w;
    atomicAdd(&g_z[(size_t)r * 128 + 64 + lane], ev * ec0);
    atomicAdd(&g_z[(size_t)r * 128 + 96 + lane], ev * ec1);
}

// ---------------- final logits + log_softmax ----------------
__global__ void logits_kernel(const float* __restrict__ w2, const float* __restrict__ b2,
                              float* __restrict__ out) {
    int gid = blockIdx.x * 256 + threadIdx.x;
    int n = gid >> 5;
    if (n >= NNODE) return;
    int lane = gid & 31;
    float v0 = g_x2all[(size_t)n * 64 + lane];
    float v1 = g_x2all[(size_t)n * 64 + 32 + lane];
    float l0 = v0 * w2[lane * 2 + 0] + v1 * w2[(lane + 32) * 2 + 0];
    float l1 = v0 * w2[lane * 2 + 1] + v1 * w2[(lane + 32) * 2 + 1];
#pragma unroll
    for (int o = 16; o > 0; o >>= 1) {
        l0 += __shfl_down_sync(0xffffffffu, l0, o);
        l1 += __shfl_down_sync(0xffffffffu, l1, o);
    }
    if (lane == 0) {
        l0 += b2[0];
        l1 += b2[1];
        float m = fmaxf(l0, l1);
        float lse = m + logf(expf(l0 - m) + expf(l1 - m));
        out[(size_t)n * 2 + 0] = l0 - lse;
        out[(size_t)n * 2 + 1] = l1 - lse;
    }
}

// ---------------- host launch ----------------
extern "C" void kernel_launch(void* const* d_in, const int* in_sizes, int n_in,
                              void* d_out, int out_size) {
    const int* adj_idx = (const int*)d_in[0];
    const float* adj_val = (const float*)d_in[1];
    const int* p_start = (const int*)d_in[2];
    const int* p_end = (const int*)d_in[3];
    const float* W1 = (const float*)d_in[4];
    const float* b1 = (const float*)d_in[5];
    const float* W2 = (const float*)d_in[6];
    const float* b2 = (const float*)d_in[7];
    const float* w_ih = (const float*)d_in[8];
    const float* w_hh = (const float*)d_in[9];
    const float* b_ih = (const float*)d_in[10];
    const float* b_hh = (const float*)d_in[11];
    const float* bn_gamma = (const float*)d_in[12];
    const float* bn_beta = (const float*)d_in[13];
    const float* attn_w = (const float*)d_in[14];
    const float* attn_b = (const float*)d_in[15];
    const float* np_w1 = (const float*)d_in[16];
    const float* np_b1 = (const float*)d_in[17];
    const float* np_w2 = (const float*)d_in[18];
    const float* np_b2 = (const float*)d_in[19];
    float* out = (float*)d_out;

    float *x2all, *gxall, *hA, *hB, *z;
    cudaGetSymbolAddress((void**)&x2all, g_x2all);
    cudaGetSymbolAddress((void**)&gxall, g_gxall);
    cudaGetSymbolAddress((void**)&hA, g_hA);
    cudaGetSymbolAddress((void**)&hB, g_hB);
    cudaGetSymbolAddress((void**)&z, g_z);

    const int SMEM_K1 = 64 * 68 * 4 + 2 * 128 * 72 * 4;  // 91136
    const int SMEM_K3 = 4 * 32 * 52 * 8;                 // 53248 (B only)
    cudaFuncSetAttribute(gcn_mma_all_kernel, cudaFuncAttributeMaxDynamicSharedMemorySize, SMEM_K1);
    cudaFuncSetAttribute(np_mma_kernel, cudaFuncAttributeMaxDynamicSharedMemorySize, SMEM_K1);
    cudaFuncSetAttribute(gru_mma_kernel<false>, cudaFuncAttributeMaxDynamicSharedMemorySize, SMEM_K3);
    cudaFuncSetAttribute(gru_mma_kernel<true>, cudaFuncAttributeMaxDynamicSharedMemorySize, SMEM_K3);

    // prep + CSR build
    prep_kernel<<<(PREP_TOTAL + 255) / 256, 256>>>(w_ih, w_hh, W2, np_w1);
    csr_count_kernel<<<(SDAYS * NEDGE + 255) / 256, 256>>>(adj_idx);
    csr_scan_block_kernel<<<dim3(BPD, SDAYS), 256>>>();
    csr_apply_kernel<<<dim3((NNODE + 255) / 256, SDAYS), 256>>>();
    csr_scatter_kernel<<<(SDAYS * NEDGE + 255) / 256, 256>>>(adj_idx, adj_val);

    // ---- precompute ALL 7 days of the h-independent input path ----
    spmm1_gather_kernel<<<dim3(NNODE / 8, NSTEP), 256>>>(p_start, W1, b1);
    gcn_mma_all_kernel<<<296, 256, SMEM_K1>>>();
    spmm2_gather_kernel<<<dim3(NNODE / 16, NSTEP), 256>>>(p_start, b2);

    // ---- 7 sequential GRU steps; t=0 specialized (h==0); h & gx in pair layout ----
    gru_mma_kernel<true><<<dim3(111, 4), 256, SMEM_K3>>>(gxall, hA, hB, b_ih, b_hh, NTILES);
    for (int t = 1; t < NSTEP; t++) {
        const float* hr = (t & 1) ? hB : hA;
        float* hw = (t & 1) ? hA : hB;
        gru_mma_kernel<false><<<dim3(111, 4), 256, SMEM_K3>>>(gxall + (size_t)t * NNODE * 64, hr,
                                                              hw, b_ih, b_hh, NTILES);
    }
    // after t=6 (even), final hidden state is in hB (pair layout)

    // ---- batch norm -> z[:, 0:64] (position->column remap inside) ----
    bn_stats_kernel<<<128, 256>>>(hB);
    bn_norm_kernel<<<(NNODE * 64 + 255) / 256, 256>>>(hB, bn_gamma, bn_beta);

    // ---- attention on day end_day+1 -> z[:, 64:128] (deg from cnt-self) ----
    attn_kernel<<<(NEDGE * 32 + 255) / 256, 256>>>(adj_idx, p_end, attn_w, attn_b);

    // ---- node predictor head + logits ----
    np_mma_kernel<<<296, 256, SMEM_K1>>>(z, x2all, np_b1);
    logits_kernel<<<(NNODE * 32 + 255) / 256, 256>>>(np_w2, np_b2, out);
}